// round 5
// baseline (speedup 1.0000x reference)
#include <cuda_runtime.h>
#include <math.h>

// Problem constants
#define BSZ 2
#define SSZ 2048
#define DIM 1024
#define NHEAD 16
#define HDIM 64
#define MROWS (BSZ * SSZ)   // 4096

// -------------------- scratch (__device__ globals; no allocation) -----------
__device__ float g_q [MROWS * DIM];
__device__ float g_k [MROWS * DIM];
__device__ float g_v [MROWS * DIM];
__device__ float g_c1[MROWS * DIM];   // depthwise conv out
__device__ float g_c2[MROWS * DIM];   // pointwise conv + GELU out
__device__ float g_at[MROWS * DIM];   // attention out (pre o-proj)
__device__ float g_ao[MROWS * DIM];   // after wo

// ===================== SGEMM (NT): C[m,n] = sum_k A[m,k] * W[n,k] + bias[n] =
// A can be split across two buffers along K (for the fusion concat):
//   k <  ksplit -> A0[m, k]
//   k >= ksplit -> A1[m, k - ksplit]
// ACT: 0 = none, 1 = exact GELU
// Tile: 128x128, k-step 16, 256 threads, 8x8 register tile per thread.
template<int ACT>
__global__ __launch_bounds__(256) void gemm_nt(
    const float* __restrict__ A0, const float* __restrict__ A1, int ksplit,
    const float* __restrict__ W, int ldw,
    const float* __restrict__ bias, float* __restrict__ Cc,
    int M, int N, int K, int lda)
{
    __shared__ float As[16][128];
    __shared__ float Bs[16][128];

    const int tid = threadIdx.x;
    const int m0 = blockIdx.y * 128;
    const int n0 = blockIdx.x * 128;
    const int tm = (tid >> 4) * 8;    // compute tile row base
    const int tn = (tid & 15) * 8;    // compute tile col base

    // loader mapping: two sub-loads, idx = tid + 256*i in [0, 512)
    //   row = idx & 127   (consecutive rows within a warp -> conflict-free STS)
    //   kq  = (idx >> 7) * 4
    const int row0 = tid & 127;
    const int kq0  = (tid >> 7) * 4;          // 0 or 4
    const int row1 = row0;
    const int kq1  = kq0 + 8;                 // 8 or 12

    float acc[8][8];
#pragma unroll
    for (int i = 0; i < 8; i++)
#pragma unroll
        for (int j = 0; j < 8; j++) acc[i][j] = 0.0f;

    for (int k0 = 0; k0 < K; k0 += 16) {
        const int kkA0 = k0 + kq0;
        const int kkA1 = k0 + kq1;
        const float* ap0 = (kkA0 < ksplit)
            ? (A0 + (size_t)(m0 + row0) * lda + kkA0)
            : (A1 + (size_t)(m0 + row0) * lda + (kkA0 - ksplit));
        const float* ap1 = (kkA1 < ksplit)
            ? (A0 + (size_t)(m0 + row1) * lda + kkA1)
            : (A1 + (size_t)(m0 + row1) * lda + (kkA1 - ksplit));
        const float4 av0 = *(const float4*)ap0;
        const float4 av1 = *(const float4*)ap1;
        const float4 bv0 = *(const float4*)(W + (size_t)(n0 + row0) * ldw + kkA0);
        const float4 bv1 = *(const float4*)(W + (size_t)(n0 + row1) * ldw + kkA1);

        __syncthreads();   // previous iteration's compute done
        As[kq0 + 0][row0] = av0.x; As[kq0 + 1][row0] = av0.y;
        As[kq0 + 2][row0] = av0.z; As[kq0 + 3][row0] = av0.w;
        As[kq1 + 0][row1] = av1.x; As[kq1 + 1][row1] = av1.y;
        As[kq1 + 2][row1] = av1.z; As[kq1 + 3][row1] = av1.w;
        Bs[kq0 + 0][row0] = bv0.x; Bs[kq0 + 1][row0] = bv0.y;
        Bs[kq0 + 2][row0] = bv0.z; Bs[kq0 + 3][row0] = bv0.w;
        Bs[kq1 + 0][row1] = bv1.x; Bs[kq1 + 1][row1] = bv1.y;
        Bs[kq1 + 2][row1] = bv1.z; Bs[kq1 + 3][row1] = bv1.w;
        __syncthreads();

#pragma unroll
        for (int k = 0; k < 16; k++) {
            float a[8], b[8];
            *(float4*)&a[0] = *(const float4*)&As[k][tm];
            *(float4*)&a[4] = *(const float4*)&As[k][tm + 4];
            *(float4*)&b[0] = *(const float4*)&Bs[k][tn];
            *(float4*)&b[4] = *(const float4*)&Bs[k][tn + 4];
#pragma unroll
            for (int i = 0; i < 8; i++)
#pragma unroll
                for (int j = 0; j < 8; j++)
                    acc[i][j] = fmaf(a[i], b[j], acc[i][j]);
        }
    }

    // epilogue: bias (+ optional exact GELU), float4 stores
#pragma unroll
    for (int i = 0; i < 8; i++) {
        float vout[8];
#pragma unroll
        for (int j = 0; j < 8; j++) {
            float v = acc[i][j] + bias[n0 + tn + j];
            if (ACT == 1)
                v = 0.5f * v * (1.0f + erff(v * 0.70710678118654752f));
            vout[j] = v;
        }
        float* cp = Cc + (size_t)(m0 + tm + i) * N + n0 + tn;
        *(float4*)(cp)     = make_float4(vout[0], vout[1], vout[2], vout[3]);
        *(float4*)(cp + 4) = make_float4(vout[4], vout[5], vout[6], vout[7]);
    }
}

// ===================== depthwise conv (K=3, pad=1) along S =================
// x: [B, S, C]; w: [C, 1, 3]; y: [B, S, C]
__global__ void dwconv_kernel(
    const float* __restrict__ x, const float* __restrict__ w,
    const float* __restrict__ bias, float* __restrict__ y)
{
    const int C4 = DIM / 4;
    int idx = blockIdx.x * blockDim.x + threadIdx.x;
    if (idx >= BSZ * SSZ * C4) return;
    const int c  = (idx % C4) * 4;
    const int bs = idx / C4;
    const int s  = bs & (SSZ - 1);

    float4 acc;
    acc.x = bias[c]; acc.y = bias[c + 1]; acc.z = bias[c + 2]; acc.w = bias[c + 3];
#pragma unroll
    for (int j = 0; j < 3; j++) {
        const int ss = s - 1 + j;
        if (ss < 0 || ss >= SSZ) continue;
        const float4 xv = *(const float4*)(x + (size_t)(bs + (j - 1)) * DIM + c);
        acc.x += xv.x * w[(c + 0) * 3 + j];
        acc.y += xv.y * w[(c + 1) * 3 + j];
        acc.z += xv.z * w[(c + 2) * 3 + j];
        acc.w += xv.w * w[(c + 3) * 3 + j];
    }
    *(float4*)(y + (size_t)bs * DIM + c) = acc;
}

// ===================== flash attention, fp32, BM=BN=64, hd=64 ==============
__device__ __forceinline__ float redmax16(float v) {
#pragma unroll
    for (int o = 8; o > 0; o >>= 1)
        v = fmaxf(v, __shfl_xor_sync(0xffffffffu, v, o, 16));
    return v;
}
__device__ __forceinline__ float redsum16(float v) {
#pragma unroll
    for (int o = 8; o > 0; o >>= 1)
        v += __shfl_xor_sync(0xffffffffu, v, o, 16);
    return v;
}

// smem: Qs [64][65] (hd-major), Ks [64][65] (hd-major), Vs [64][64] (key-major),
//       Ps [64][64] (row-major). Total 66048 bytes (dynamic).
__global__ __launch_bounds__(256) void flash_attn(
    const float* __restrict__ Qg, const float* __restrict__ Kg,
    const float* __restrict__ Vg, float* __restrict__ Og)
{
    extern __shared__ float sm[];
    float* Qs = sm;                 // [k][r]   stride 65
    float* Ks = sm + 64 * 65;       // [k][c]   stride 65
    float* Vs = sm + 2 * 64 * 65;   // [key][c] stride 64
    float* Ps = Vs + 64 * 64;       // [r][key] stride 64

    const int tid = threadIdx.x;
    const int ty = tid >> 4, tx = tid & 15;
    const int bh = blockIdx.y;
    const int b = bh >> 4, h = bh & 15;
    const int q0 = blockIdx.x * 64;

    const float* qb = Qg + ((size_t)(b * SSZ + q0)) * DIM + h * HDIM;

    // load Q transposed into Qs[k][r]
#pragma unroll
    for (int it = 0; it < 4; it++) {
        const int r = (tid >> 4) + it * 16;
        const int c = (tid & 15) * 4;
        const float4 v = *(const float4*)(qb + (size_t)r * DIM + c);
        Qs[(c + 0) * 65 + r] = v.x;
        Qs[(c + 1) * 65 + r] = v.y;
        Qs[(c + 2) * 65 + r] = v.z;
        Qs[(c + 3) * 65 + r] = v.w;
    }

    float m_i[4], l_i[4], o[4][4];
#pragma unroll
    for (int i = 0; i < 4; i++) {
        m_i[i] = -1e30f; l_i[i] = 0.0f;
#pragma unroll
        for (int j = 0; j < 4; j++) o[i][j] = 0.0f;
    }

    for (int t = 0; t < SSZ / 64; t++) {
        __syncthreads();   // prior PV done before overwriting K/V tiles
        const float* kb = Kg + ((size_t)(b * SSZ + t * 64)) * DIM + h * HDIM;
        const float* vb = Vg + ((size_t)(b * SSZ + t * 64)) * DIM + h * HDIM;
#pragma unroll
        for (int it = 0; it < 4; it++) {
            const int r = (tid >> 4) + it * 16;
            const int c = (tid & 15) * 4;
            const float4 kv = *(const float4*)(kb + (size_t)r * DIM + c);
            Ks[(c + 0) * 65 + r] = kv.x;
            Ks[(c + 1) * 65 + r] = kv.y;
            Ks[(c + 2) * 65 + r] = kv.z;
            Ks[(c + 3) * 65 + r] = kv.w;
            const float4 vv = *(const float4*)(vb + (size_t)r * DIM + c);
            *(float4*)&Vs[r * 64 + c] = vv;
        }
        __syncthreads();

        // S = (Q K^T) / sqrt(hd): thread tile [4 rows][4 keys]
        float s[4][4];
#pragma unroll
        for (int i = 0; i < 4; i++)
#pragma unroll
            for (int j = 0; j < 4; j++) s[i][j] = 0.0f;

#pragma unroll 8
        for (int k = 0; k < HDIM; k++) {
            float a[4], bb[4];
#pragma unroll
            for (int i = 0; i < 4; i++) a[i]  = Qs[k * 65 + ty * 4 + i];
#pragma unroll
            for (int j = 0; j < 4; j++) bb[j] = Ks[k * 65 + tx * 4 + j];
#pragma unroll
            for (int i = 0; i < 4; i++)
#pragma unroll
                for (int j = 0; j < 4; j++)
                    s[i][j] = fmaf(a[i], bb[j], s[i][j]);
        }

        // online softmax
        float rs[4];
#pragma unroll
        for (int i = 0; i < 4; i++) {
            float mt = -1e30f;
#pragma unroll
            for (int j = 0; j < 4; j++) {
                s[i][j] *= 0.125f;             // 1/sqrt(64)
                mt = fmaxf(mt, s[i][j]);
            }
            mt = redmax16(mt);
            const float mn = fmaxf(m_i[i], mt);
            const float al = __expf(m_i[i] - mn);
            float r = 0.0f;
#pragma unroll
            for (int j = 0; j < 4; j++) {
                const float p = __expf(s[i][j] - mn);
                s[i][j] = p; r += p;
            }
            r = redsum16(r);
            l_i[i] = l_i[i] * al + r;
            m_i[i] = mn;
            rs[i] = al;
        }
#pragma unroll
        for (int i = 0; i < 4; i++)
#pragma unroll
            for (int j = 0; j < 4; j++) o[i][j] *= rs[i];

        // stage P to smem
#pragma unroll
        for (int i = 0; i < 4; i++)
#pragma unroll
            for (int j = 0; j < 4; j++)
                Ps[(ty * 4 + i) * 64 + tx * 4 + j] = s[i][j];
        __syncthreads();

        // O += P V : contraction over 64 keys
#pragma unroll 8
        for (int kk = 0; kk < 64; kk++) {
            float pa[4], vv[4];
#pragma unroll
            for (int i = 0; i < 4; i++) pa[i] = Ps[(ty * 4 + i) * 64 + kk];
#pragma unroll
            for (int j = 0; j < 4; j++) vv[j] = Vs[kk * 64 + tx * 4 + j];
#pragma unroll
            for (int i = 0; i < 4; i++)
#pragma unroll
                for (int j = 0; j < 4; j++)
                    o[i][j] = fmaf(pa[i], vv[j], o[i][j]);
        }
    }

    // write O / l
    float* ob = Og + ((size_t)(b * SSZ + q0)) * DIM + h * HDIM;
#pragma unroll
    for (int i = 0; i < 4; i++) {
        const float inv = 1.0f / l_i[i];
#pragma unroll
        for (int j = 0; j < 4; j++)
            ob[(size_t)(ty * 4 + i) * DIM + tx * 4 + j] = o[i][j] * inv;
    }
}

// ===================== launcher ============================================
extern "C" void kernel_launch(void* const* d_in, const int* in_sizes, int n_in,
                              void* d_out, int out_size)
{
    const float* x    = (const float*)d_in[0];
    const float* wq   = (const float*)d_in[1];
    const float* bq   = (const float*)d_in[2];
    const float* wk   = (const float*)d_in[3];
    const float* bk   = (const float*)d_in[4];
    const float* wv   = (const float*)d_in[5];
    const float* bv   = (const float*)d_in[6];
    const float* wo   = (const float*)d_in[7];
    const float* bo   = (const float*)d_in[8];
    const float* dw_w = (const float*)d_in[9];
    const float* dw_b = (const float*)d_in[10];
    const float* pw_w = (const float*)d_in[11];
    const float* pw_b = (const float*)d_in[12];
    const float* fu_w = (const float*)d_in[13];
    const float* fu_b = (const float*)d_in[14];
    float* out = (float*)d_out;

    float *q, *k, *v, *c1, *c2, *at, *ao;
    cudaGetSymbolAddress((void**)&q,  g_q);
    cudaGetSymbolAddress((void**)&k,  g_k);
    cudaGetSymbolAddress((void**)&v,  g_v);
    cudaGetSymbolAddress((void**)&c1, g_c1);
    cudaGetSymbolAddress((void**)&c2, g_c2);
    cudaGetSymbolAddress((void**)&at, g_at);
    cudaGetSymbolAddress((void**)&ao, g_ao);

    const dim3 gg(DIM / 128, MROWS / 128);   // (8, 32)
    const int BIG = 1 << 30;

    // Q/K/V projections
    gemm_nt<0><<<gg, 256>>>(x, x, BIG, wq, DIM, bq, q, MROWS, DIM, DIM, DIM);
    gemm_nt<0><<<gg, 256>>>(x, x, BIG, wk, DIM, bk, k, MROWS, DIM, DIM, DIM);
    gemm_nt<0><<<gg, 256>>>(x, x, BIG, wv, DIM, bv, v, MROWS, DIM, DIM, DIM);

    // conv branch
    const int dwthreads = BSZ * SSZ * (DIM / 4);
    dwconv_kernel<<<(dwthreads + 255) / 256, 256>>>(x, dw_w, dw_b, c1);
    gemm_nt<1><<<gg, 256>>>(c1, c1, BIG, pw_w, DIM, pw_b, c2, MROWS, DIM, DIM, DIM);

    // attention
    const size_t fsm = (size_t)(2 * 64 * 65 + 2 * 64 * 64) * sizeof(float);
    cudaFuncSetAttribute(flash_attn, cudaFuncAttributeMaxDynamicSharedMemorySize,
                         (int)fsm);
    flash_attn<<<dim3(SSZ / 64, BSZ * NHEAD), 256, fsm>>>(q, k, v, at);
    gemm_nt<0><<<gg, 256>>>(at, at, BIG, wo, DIM, bo, ao, MROWS, DIM, DIM, DIM);

    // fusion: concat([attn_o, conv], K) @ fu_w^T + fu_b
    // ksplit = DIM: k < 1024 reads ao, k >= 1024 reads c2.
    gemm_nt<0><<<gg, 256>>>(ao, c2, DIM, fu_w, 2 * DIM, fu_b, out,
                            MROWS, DIM, 2 * DIM, DIM);
}

// round 6
// speedup vs baseline: 1.0004x; 1.0004x over previous
#include <cuda_runtime.h>
#include <math.h>

// Problem constants
#define BSZ 2
#define SSZ 2048
#define DIM 1024
#define NHEAD 16
#define HDIM 64
#define MROWS (BSZ * SSZ)   // 4096

// ---- packed f32x2 helpers (FFMA2 path; ptxas never auto-generates) --------
#define FMA2(d, a, b) \
    asm("fma.rn.f32x2 %0, %1, %2, %0;" : "+l"(d) : "l"(a), "l"(b))
#define MUL2(d, a) \
    asm("mul.rn.f32x2 %0, %0, %1;" : "+l"(d) : "l"(a))
#define DUP2(d, f) \
    asm("mov.b64 %0, {%1, %1};" : "=l"(d) : "r"(__float_as_uint(f)))
#define UNPK2(lo, hi, v) \
    do { unsigned int _u0, _u1; \
         asm("mov.b64 {%0, %1}, %2;" : "=r"(_u0), "=r"(_u1) : "l"(v)); \
         lo = __uint_as_float(_u0); hi = __uint_as_float(_u1); } while (0)

typedef unsigned long long u64t;

// -------------------- scratch (__device__ globals; no allocation) -----------
__device__ float g_q [MROWS * DIM];
__device__ float g_k [MROWS * DIM];
__device__ float g_v [MROWS * DIM];
__device__ float g_c1[MROWS * DIM];   // depthwise conv out
__device__ float g_c2[MROWS * DIM];   // pointwise conv + GELU out
__device__ float g_at[MROWS * DIM];   // attention out (pre o-proj)
__device__ float g_ao[MROWS * DIM];   // after wo

// ===================== SGEMM (NT): C[m,n] = sum_k A[m,k] * W[n,k] + bias[n] =
// A split across two buffers along K (fusion concat): k < ksplit -> A0, else A1.
// ACT: 0 = none, 1 = exact GELU
// Tile: 128x128, k-step 16, 256 threads, 8x8 register tile, packed FFMA2.
template<int ACT>
__global__ __launch_bounds__(256) void gemm_nt(
    const float* __restrict__ A0, const float* __restrict__ A1, int ksplit,
    const float* __restrict__ W, int ldw,
    const float* __restrict__ bias, float* __restrict__ Cc,
    int M, int N, int K, int lda)
{
    __shared__ float As[16][128];
    __shared__ float Bs[16][128];

    const int tid = threadIdx.x;
    const int m0 = blockIdx.y * 128;
    const int n0 = blockIdx.x * 128;
    const int tm = (tid >> 4) * 8;    // compute tile row base
    const int tn = (tid & 15) * 8;    // compute tile col base

    const int row0 = tid & 127;
    const int kq0  = (tid >> 7) * 4;          // 0 or 4
    const int kq1  = kq0 + 8;                 // 8 or 12

    // accumulators: 8 rows x 4 packed column-pairs
    u64t acc2[8][4];
#pragma unroll
    for (int i = 0; i < 8; i++)
#pragma unroll
        for (int j = 0; j < 4; j++) acc2[i][j] = 0ull;

    for (int k0 = 0; k0 < K; k0 += 16) {
        const int kkA0 = k0 + kq0;
        const int kkA1 = k0 + kq1;
        const float* ap0 = (kkA0 < ksplit)
            ? (A0 + (size_t)(m0 + row0) * lda + kkA0)
            : (A1 + (size_t)(m0 + row0) * lda + (kkA0 - ksplit));
        const float* ap1 = (kkA1 < ksplit)
            ? (A0 + (size_t)(m0 + row0) * lda + kkA1)
            : (A1 + (size_t)(m0 + row0) * lda + (kkA1 - ksplit));
        const float4 av0 = *(const float4*)ap0;
        const float4 av1 = *(const float4*)ap1;
        const float4 bv0 = *(const float4*)(W + (size_t)(n0 + row0) * ldw + kkA0);
        const float4 bv1 = *(const float4*)(W + (size_t)(n0 + row0) * ldw + kkA1);

        __syncthreads();   // previous iteration's compute done
        As[kq0 + 0][row0] = av0.x; As[kq0 + 1][row0] = av0.y;
        As[kq0 + 2][row0] = av0.z; As[kq0 + 3][row0] = av0.w;
        As[kq1 + 0][row0] = av1.x; As[kq1 + 1][row0] = av1.y;
        As[kq1 + 2][row0] = av1.z; As[kq1 + 3][row0] = av1.w;
        Bs[kq0 + 0][row0] = bv0.x; Bs[kq0 + 1][row0] = bv0.y;
        Bs[kq0 + 2][row0] = bv0.z; Bs[kq0 + 3][row0] = bv0.w;
        Bs[kq1 + 0][row0] = bv1.x; Bs[kq1 + 1][row0] = bv1.y;
        Bs[kq1 + 2][row0] = bv1.z; Bs[kq1 + 3][row0] = bv1.w;
        __syncthreads();

#pragma unroll
        for (int k = 0; k < 16; k++) {
            const float4 a0 = *(const float4*)&As[k][tm];
            const float4 a1 = *(const float4*)&As[k][tm + 4];
            const ulonglong2 b0 = *(const ulonglong2*)&Bs[k][tn];
            const ulonglong2 b1 = *(const ulonglong2*)&Bs[k][tn + 4];
            u64t ad[8];
            DUP2(ad[0], a0.x); DUP2(ad[1], a0.y);
            DUP2(ad[2], a0.z); DUP2(ad[3], a0.w);
            DUP2(ad[4], a1.x); DUP2(ad[5], a1.y);
            DUP2(ad[6], a1.z); DUP2(ad[7], a1.w);
#pragma unroll
            for (int i = 0; i < 8; i++) {
                FMA2(acc2[i][0], ad[i], b0.x);
                FMA2(acc2[i][1], ad[i], b0.y);
                FMA2(acc2[i][2], ad[i], b1.x);
                FMA2(acc2[i][3], ad[i], b1.y);
            }
        }
    }

    // epilogue: unpack, bias (+ optional exact GELU), float4 stores
#pragma unroll
    for (int i = 0; i < 8; i++) {
        float vout[8];
#pragma unroll
        for (int jp = 0; jp < 4; jp++)
            UNPK2(vout[2 * jp], vout[2 * jp + 1], acc2[i][jp]);
#pragma unroll
        for (int j = 0; j < 8; j++) {
            float v = vout[j] + bias[n0 + tn + j];
            if (ACT == 1)
                v = 0.5f * v * (1.0f + erff(v * 0.70710678118654752f));
            vout[j] = v;
        }
        float* cp = Cc + (size_t)(m0 + tm + i) * N + n0 + tn;
        *(float4*)(cp)     = make_float4(vout[0], vout[1], vout[2], vout[3]);
        *(float4*)(cp + 4) = make_float4(vout[4], vout[5], vout[6], vout[7]);
    }
}

// ===================== depthwise conv (K=3, pad=1) along S =================
__global__ void dwconv_kernel(
    const float* __restrict__ x, const float* __restrict__ w,
    const float* __restrict__ bias, float* __restrict__ y)
{
    const int C4 = DIM / 4;
    int idx = blockIdx.x * blockDim.x + threadIdx.x;
    if (idx >= BSZ * SSZ * C4) return;
    const int c  = (idx % C4) * 4;
    const int bs = idx / C4;
    const int s  = bs & (SSZ - 1);

    float4 acc;
    acc.x = bias[c]; acc.y = bias[c + 1]; acc.z = bias[c + 2]; acc.w = bias[c + 3];
#pragma unroll
    for (int j = 0; j < 3; j++) {
        const int ss = s - 1 + j;
        if (ss < 0 || ss >= SSZ) continue;
        const float4 xv = *(const float4*)(x + (size_t)(bs + (j - 1)) * DIM + c);
        acc.x += xv.x * w[(c + 0) * 3 + j];
        acc.y += xv.y * w[(c + 1) * 3 + j];
        acc.z += xv.z * w[(c + 2) * 3 + j];
        acc.w += xv.w * w[(c + 3) * 3 + j];
    }
    *(float4*)(y + (size_t)bs * DIM + c) = acc;
}

// ===================== flash attention, fp32 FFMA2, BM=BN=64, hd=64 ========
__device__ __forceinline__ float redmax16(float v) {
#pragma unroll
    for (int o = 8; o > 0; o >>= 1)
        v = fmaxf(v, __shfl_xor_sync(0xffffffffu, v, o, 16));
    return v;
}
__device__ __forceinline__ float redsum16(float v) {
#pragma unroll
    for (int o = 8; o > 0; o >>= 1)
        v += __shfl_xor_sync(0xffffffffu, v, o, 16);
    return v;
}

#define QKS 68   // stride for transposed Q/K tiles: 68*4 = 272 B, 16B-aligned rows

// smem: Qs [64][68] (hd-major), Ks [64][68] (hd-major), Vs [64][64] (key-major),
//       Ps [64][64] (row-major). Total 67584 bytes (dynamic).
__global__ __launch_bounds__(256) void flash_attn(
    const float* __restrict__ Qg, const float* __restrict__ Kg,
    const float* __restrict__ Vg, float* __restrict__ Og)
{
    extern __shared__ float sm[];
    float* Qs = sm;                  // [k][r]   stride QKS
    float* Ks = sm + 64 * QKS;       // [k][c]   stride QKS
    float* Vs = sm + 2 * 64 * QKS;   // [key][c] stride 64
    float* Ps = Vs + 64 * 64;        // [r][key] stride 64

    const int tid = threadIdx.x;
    const int ty = tid >> 4, tx = tid & 15;
    const int bh = blockIdx.y;
    const int b = bh >> 4, h = bh & 15;
    const int q0 = blockIdx.x * 64;

    const float* qb = Qg + ((size_t)(b * SSZ + q0)) * DIM + h * HDIM;

    // load Q transposed into Qs[k][r]
#pragma unroll
    for (int it = 0; it < 4; it++) {
        const int r = (tid >> 4) + it * 16;
        const int c = (tid & 15) * 4;
        const float4 v = *(const float4*)(qb + (size_t)r * DIM + c);
        Qs[(c + 0) * QKS + r] = v.x;
        Qs[(c + 1) * QKS + r] = v.y;
        Qs[(c + 2) * QKS + r] = v.z;
        Qs[(c + 3) * QKS + r] = v.w;
    }

    float m_i[4], l_i[4];
    u64t  o2[4][2];   // packed O accumulators: 4 rows x 2 col-pairs
#pragma unroll
    for (int i = 0; i < 4; i++) {
        m_i[i] = -1e30f; l_i[i] = 0.0f;
        o2[i][0] = 0ull; o2[i][1] = 0ull;
    }

    for (int t = 0; t < SSZ / 64; t++) {
        __syncthreads();   // prior PV done before overwriting K/V tiles
        const float* kb = Kg + ((size_t)(b * SSZ + t * 64)) * DIM + h * HDIM;
        const float* vb = Vg + ((size_t)(b * SSZ + t * 64)) * DIM + h * HDIM;
#pragma unroll
        for (int it = 0; it < 4; it++) {
            const int r = (tid >> 4) + it * 16;
            const int c = (tid & 15) * 4;
            const float4 kv = *(const float4*)(kb + (size_t)r * DIM + c);
            Ks[(c + 0) * QKS + r] = kv.x;
            Ks[(c + 1) * QKS + r] = kv.y;
            Ks[(c + 2) * QKS + r] = kv.z;
            Ks[(c + 3) * QKS + r] = kv.w;
            const float4 vv = *(const float4*)(vb + (size_t)r * DIM + c);
            *(float4*)&Vs[r * 64 + c] = vv;
        }
        __syncthreads();

        // S = (Q K^T): packed thread tile [4 rows][2 key-pairs]
        u64t s2[4][2];
#pragma unroll
        for (int i = 0; i < 4; i++) { s2[i][0] = 0ull; s2[i][1] = 0ull; }

#pragma unroll 4
        for (int k = 0; k < HDIM; k++) {
            const float4 av = *(const float4*)&Qs[k * QKS + ty * 4];
            const ulonglong2 bv = *(const ulonglong2*)&Ks[k * QKS + tx * 4];
            u64t ad[4];
            DUP2(ad[0], av.x); DUP2(ad[1], av.y);
            DUP2(ad[2], av.z); DUP2(ad[3], av.w);
#pragma unroll
            for (int i = 0; i < 4; i++) {
                FMA2(s2[i][0], ad[i], bv.x);
                FMA2(s2[i][1], ad[i], bv.y);
            }
        }

        // unpack scores, online softmax
        float s[4][4], rs[4];
#pragma unroll
        for (int i = 0; i < 4; i++) {
            UNPK2(s[i][0], s[i][1], s2[i][0]);
            UNPK2(s[i][2], s[i][3], s2[i][1]);
        }
#pragma unroll
        for (int i = 0; i < 4; i++) {
            float mt = -1e30f;
#pragma unroll
            for (int j = 0; j < 4; j++) {
                s[i][j] *= 0.125f;             // 1/sqrt(64)
                mt = fmaxf(mt, s[i][j]);
            }
            mt = redmax16(mt);
            const float mn = fmaxf(m_i[i], mt);
            const float al = __expf(m_i[i] - mn);
            float r = 0.0f;
#pragma unroll
            for (int j = 0; j < 4; j++) {
                const float p = __expf(s[i][j] - mn);
                s[i][j] = p; r += p;
            }
            r = redsum16(r);
            l_i[i] = l_i[i] * al + r;
            m_i[i] = mn;
            rs[i] = al;
        }
#pragma unroll
        for (int i = 0; i < 4; i++) {
            u64t rsd; DUP2(rsd, rs[i]);
            MUL2(o2[i][0], rsd);
            MUL2(o2[i][1], rsd);
        }

        // stage P to smem
#pragma unroll
        for (int i = 0; i < 4; i++)
#pragma unroll
            for (int j = 0; j < 4; j++)
                Ps[(ty * 4 + i) * 64 + tx * 4 + j] = s[i][j];
        __syncthreads();

        // O += P V : contraction over 64 keys, packed
#pragma unroll 4
        for (int kk = 0; kk < 64; kk++) {
            const ulonglong2 vv = *(const ulonglong2*)&Vs[kk * 64 + tx * 4];
            u64t pd[4];
            DUP2(pd[0], Ps[(ty * 4 + 0) * 64 + kk]);
            DUP2(pd[1], Ps[(ty * 4 + 1) * 64 + kk]);
            DUP2(pd[2], Ps[(ty * 4 + 2) * 64 + kk]);
            DUP2(pd[3], Ps[(ty * 4 + 3) * 64 + kk]);
#pragma unroll
            for (int i = 0; i < 4; i++) {
                FMA2(o2[i][0], pd[i], vv.x);
                FMA2(o2[i][1], pd[i], vv.y);
            }
        }
    }

    // write O / l
    float* ob = Og + ((size_t)(b * SSZ + q0)) * DIM + h * HDIM;
#pragma unroll
    for (int i = 0; i < 4; i++) {
        const float inv = 1.0f / l_i[i];
        float o[4];
        UNPK2(o[0], o[1], o2[i][0]);
        UNPK2(o[2], o[3], o2[i][1]);
#pragma unroll
        for (int j = 0; j < 4; j++)
            ob[(size_t)(ty * 4 + i) * DIM + tx * 4 + j] = o[j] * inv;
    }
}

// ===================== launcher ============================================
extern "C" void kernel_launch(void* const* d_in, const int* in_sizes, int n_in,
                              void* d_out, int out_size)
{
    const float* x    = (const float*)d_in[0];
    const float* wq   = (const float*)d_in[1];
    const float* bq   = (const float*)d_in[2];
    const float* wk   = (const float*)d_in[3];
    const float* bk   = (const float*)d_in[4];
    const float* wv   = (const float*)d_in[5];
    const float* bv   = (const float*)d_in[6];
    const float* wo   = (const float*)d_in[7];
    const float* bo   = (const float*)d_in[8];
    const float* dw_w = (const float*)d_in[9];
    const float* dw_b = (const float*)d_in[10];
    const float* pw_w = (const float*)d_in[11];
    const float* pw_b = (const float*)d_in[12];
    const float* fu_w = (const float*)d_in[13];
    const float* fu_b = (const float*)d_in[14];
    float* out = (float*)d_out;

    float *q, *k, *v, *c1, *c2, *at, *ao;
    cudaGetSymbolAddress((void**)&q,  g_q);
    cudaGetSymbolAddress((void**)&k,  g_k);
    cudaGetSymbolAddress((void**)&v,  g_v);
    cudaGetSymbolAddress((void**)&c1, g_c1);
    cudaGetSymbolAddress((void**)&c2, g_c2);
    cudaGetSymbolAddress((void**)&at, g_at);
    cudaGetSymbolAddress((void**)&ao, g_ao);

    const dim3 gg(DIM / 128, MROWS / 128);   // (8, 32)
    const int BIG = 1 << 30;

    // Q/K/V projections
    gemm_nt<0><<<gg, 256>>>(x, x, BIG, wq, DIM, bq, q, MROWS, DIM, DIM, DIM);
    gemm_nt<0><<<gg, 256>>>(x, x, BIG, wk, DIM, bk, k, MROWS, DIM, DIM, DIM);
    gemm_nt<0><<<gg, 256>>>(x, x, BIG, wv, DIM, bv, v, MROWS, DIM, DIM, DIM);

    // conv branch
    const int dwthreads = BSZ * SSZ * (DIM / 4);
    dwconv_kernel<<<(dwthreads + 255) / 256, 256>>>(x, dw_w, dw_b, c1);
    gemm_nt<1><<<gg, 256>>>(c1, c1, BIG, pw_w, DIM, pw_b, c2, MROWS, DIM, DIM, DIM);

    // attention
    const size_t fsm = (size_t)(2 * 64 * QKS + 2 * 64 * 64) * sizeof(float);
    cudaFuncSetAttribute(flash_attn, cudaFuncAttributeMaxDynamicSharedMemorySize,
                         (int)fsm);
    flash_attn<<<dim3(SSZ / 64, BSZ * NHEAD), 256, fsm>>>(q, k, v, at);
    gemm_nt<0><<<gg, 256>>>(at, at, BIG, wo, DIM, bo, ao, MROWS, DIM, DIM, DIM);

    // fusion: concat([attn_o, conv], K) @ fu_w^T + fu_b
    // ksplit = DIM: k < 1024 reads ao, k >= 1024 reads c2.
    gemm_nt<0><<<gg, 256>>>(ao, c2, DIM, fu_w, 2 * DIM, fu_b, out,
                            MROWS, DIM, 2 * DIM, DIM);
}

// round 7
// speedup vs baseline: 1.5386x; 1.5380x over previous
#include <cuda_runtime.h>
#include <cuda_bf16.h>
#include <math.h>

// Problem constants
#define BSZ 2
#define SSZ 2048
#define DIM 1024
#define NHEAD 16
#define HDIM 64
#define MROWS (BSZ * SSZ)   // 4096

typedef unsigned int       u32;
typedef unsigned long long u64t;

// ---- packed f32x2 helpers (used by flash kernel) ---------------------------
#define FMA2(d, a, b) \
    asm("fma.rn.f32x2 %0, %1, %2, %0;" : "+l"(d) : "l"(a), "l"(b))
#define MUL2(d, a) \
    asm("mul.rn.f32x2 %0, %0, %1;" : "+l"(d) : "l"(a))
#define DUP2(d, f) \
    asm("mov.b64 %0, {%1, %1};" : "=l"(d) : "r"(__float_as_uint(f)))
#define UNPK2(lo, hi, v) \
    do { unsigned int _u0, _u1; \
         asm("mov.b64 {%0, %1}, %2;" : "=r"(_u0), "=r"(_u1) : "l"(v)); \
         lo = __uint_as_float(_u0); hi = __uint_as_float(_u1); } while (0)

// ---- bf16 mma m16n8k16, fp32 accumulate ------------------------------------
#define MMA_BF16(c, a, b0v, b1v) \
    asm("mma.sync.aligned.m16n8k16.row.col.f32.bf16.bf16.f32 " \
        "{%0,%1,%2,%3}, {%4,%5,%6,%7}, {%8,%9}, {%0,%1,%2,%3};" \
        : "+f"((c)[0]), "+f"((c)[1]), "+f"((c)[2]), "+f"((c)[3]) \
        : "r"((a)[0]), "r"((a)[1]), "r"((a)[2]), "r"((a)[3]), \
          "r"(b0v), "r"(b1v))

__device__ __forceinline__ u32 pack_bf2(__nv_bfloat16 a, __nv_bfloat16 b) {
    __nv_bfloat162 p = __halves2bfloat162(a, b);
    return *reinterpret_cast<u32*>(&p);
}

// -------------------- scratch (__device__ globals; no allocation) -----------
__device__ float g_q [MROWS * DIM];
__device__ float g_k [MROWS * DIM];
__device__ float g_v [MROWS * DIM];
__device__ float g_c1[MROWS * DIM];   // depthwise conv out
__device__ float g_c2[MROWS * DIM];   // pointwise conv + GELU out
__device__ float g_at[MROWS * DIM];   // attention out (pre o-proj)
__device__ float g_ao[MROWS * DIM];   // after wo

// ===================== GEMM (NT) via bf16-split tensor cores ================
// C[m,n] = sum_k A[m,k] * W[n,k] + bias[n]
// Split: a = a_hi + a_lo (both bf16); a*b ~= ah*bh + ah*bl + al*bh
// (lo*lo dropped, ~2^-18 relative). fp32 accumulation.
// Tile: CTA 128x128, K-chunk 32, 8 warps each 32x64, mma m16n8k16.
// A split along K at ksplit: k < ksplit -> A0, else A1 (fusion concat).
// ACT: 0 = none, 1 = exact GELU.
template<int ACT>
__global__ __launch_bounds__(256) void gemm_nt(
    const float* __restrict__ A0, const float* __restrict__ A1, int ksplit,
    const float* __restrict__ W, int ldw,
    const float* __restrict__ bias, float* __restrict__ Cc,
    int M, int N, int K, int lda)
{
    // hi/lo planes, bf16 pairs packed along k: [row][kpair], stride 20 (pad)
    __shared__ u32 Ah[128][20];
    __shared__ u32 Al[128][20];
    __shared__ u32 Bh[128][20];
    __shared__ u32 Bl[128][20];

    const int tid  = threadIdx.x;
    const int m0   = blockIdx.y * 128;
    const int n0   = blockIdx.x * 128;
    const int wid  = tid >> 5;
    const int lane = tid & 31;
    const int wm   = (wid & 3) * 32;   // warp row base: 4 warps along M
    const int wn   = (wid >> 2) * 64;  // warp col base: 2 warps along N
    const int g    = lane >> 2;        // 0..7
    const int t    = lane & 3;         // 0..3

    const int lrow = tid >> 3;         // 0..31 (+32*it)
    const int lkq  = tid & 7;          // float4 index within 32-float chunk

    float acc[2][8][4];
#pragma unroll
    for (int mt = 0; mt < 2; mt++)
#pragma unroll
        for (int nt = 0; nt < 8; nt++)
#pragma unroll
            for (int e = 0; e < 4; e++) acc[mt][nt][e] = 0.0f;

    for (int k0 = 0; k0 < K; k0 += 32) {
        __syncthreads();   // previous chunk's compute done
#pragma unroll
        for (int it = 0; it < 4; it++) {
            const int row = lrow + 32 * it;
            const int kk  = k0 + lkq * 4;
            // ---- A ----
            const float* ap = (kk < ksplit)
                ? (A0 + (size_t)(m0 + row) * lda + kk)
                : (A1 + (size_t)(m0 + row) * lda + (kk - ksplit));
            const float4 av = *(const float4*)ap;
            {
                __nv_bfloat16 hx = __float2bfloat16_rn(av.x);
                __nv_bfloat16 hy = __float2bfloat16_rn(av.y);
                __nv_bfloat16 hz = __float2bfloat16_rn(av.z);
                __nv_bfloat16 hw = __float2bfloat16_rn(av.w);
                Ah[row][lkq * 2 + 0] = pack_bf2(hx, hy);
                Ah[row][lkq * 2 + 1] = pack_bf2(hz, hw);
                Al[row][lkq * 2 + 0] = pack_bf2(
                    __float2bfloat16_rn(av.x - __bfloat162float(hx)),
                    __float2bfloat16_rn(av.y - __bfloat162float(hy)));
                Al[row][lkq * 2 + 1] = pack_bf2(
                    __float2bfloat16_rn(av.z - __bfloat162float(hz)),
                    __float2bfloat16_rn(av.w - __bfloat162float(hw)));
            }
            // ---- B (weights) ----
            const float4 bv = *(const float4*)(W + (size_t)(n0 + row) * ldw + kk);
            {
                __nv_bfloat16 hx = __float2bfloat16_rn(bv.x);
                __nv_bfloat16 hy = __float2bfloat16_rn(bv.y);
                __nv_bfloat16 hz = __float2bfloat16_rn(bv.z);
                __nv_bfloat16 hw = __float2bfloat16_rn(bv.w);
                Bh[row][lkq * 2 + 0] = pack_bf2(hx, hy);
                Bh[row][lkq * 2 + 1] = pack_bf2(hz, hw);
                Bl[row][lkq * 2 + 0] = pack_bf2(
                    __float2bfloat16_rn(bv.x - __bfloat162float(hx)),
                    __float2bfloat16_rn(bv.y - __bfloat162float(hy)));
                Bl[row][lkq * 2 + 1] = pack_bf2(
                    __float2bfloat16_rn(bv.z - __bfloat162float(hz)),
                    __float2bfloat16_rn(bv.w - __bfloat162float(hw)));
            }
        }
        __syncthreads();

#pragma unroll
        for (int ks = 0; ks < 2; ks++) {
            const int kb = ks * 8;   // kpair base for this mma k-step
            // A fragments: rows g, g+8 at kpairs (kb+t), (kb+t+4)
            u32 ah[2][4], al[2][4];
#pragma unroll
            for (int mt = 0; mt < 2; mt++) {
                const int r = wm + mt * 16;
                ah[mt][0] = Ah[r + g    ][kb + t];
                ah[mt][1] = Ah[r + 8 + g][kb + t];
                ah[mt][2] = Ah[r + g    ][kb + t + 4];
                ah[mt][3] = Ah[r + 8 + g][kb + t + 4];
                al[mt][0] = Al[r + g    ][kb + t];
                al[mt][1] = Al[r + 8 + g][kb + t];
                al[mt][2] = Al[r + g    ][kb + t + 4];
                al[mt][3] = Al[r + 8 + g][kb + t + 4];
            }
#pragma unroll
            for (int nt = 0; nt < 8; nt++) {
                const int c = wn + nt * 8;
                const u32 bh0 = Bh[c + g][kb + t];
                const u32 bh1 = Bh[c + g][kb + t + 4];
                const u32 bl0 = Bl[c + g][kb + t];
                const u32 bl1 = Bl[c + g][kb + t + 4];
#pragma unroll
                for (int mt = 0; mt < 2; mt++) {
                    MMA_BF16(acc[mt][nt], ah[mt], bh0, bh1);
                    MMA_BF16(acc[mt][nt], ah[mt], bl0, bl1);
                    MMA_BF16(acc[mt][nt], al[mt], bh0, bh1);
                }
            }
        }
    }

    // epilogue: bias (+ optional exact GELU), float2 stores
#pragma unroll
    for (int mt = 0; mt < 2; mt++) {
#pragma unroll
        for (int nt = 0; nt < 8; nt++) {
            const int row = m0 + wm + mt * 16 + g;
            const int col = n0 + wn + nt * 8 + 2 * t;
            float v0 = acc[mt][nt][0] + bias[col];
            float v1 = acc[mt][nt][1] + bias[col + 1];
            float v2 = acc[mt][nt][2] + bias[col];
            float v3 = acc[mt][nt][3] + bias[col + 1];
            if (ACT == 1) {
                v0 = 0.5f * v0 * (1.0f + erff(v0 * 0.70710678118654752f));
                v1 = 0.5f * v1 * (1.0f + erff(v1 * 0.70710678118654752f));
                v2 = 0.5f * v2 * (1.0f + erff(v2 * 0.70710678118654752f));
                v3 = 0.5f * v3 * (1.0f + erff(v3 * 0.70710678118654752f));
            }
            *(float2*)(Cc + (size_t)row * N + col)       = make_float2(v0, v1);
            *(float2*)(Cc + (size_t)(row + 8) * N + col) = make_float2(v2, v3);
        }
    }
}

// ===================== depthwise conv (K=3, pad=1) along S =================
__global__ void dwconv_kernel(
    const float* __restrict__ x, const float* __restrict__ w,
    const float* __restrict__ bias, float* __restrict__ y)
{
    const int C4 = DIM / 4;
    int idx = blockIdx.x * blockDim.x + threadIdx.x;
    if (idx >= BSZ * SSZ * C4) return;
    const int c  = (idx % C4) * 4;
    const int bs = idx / C4;
    const int s  = bs & (SSZ - 1);

    float4 acc;
    acc.x = bias[c]; acc.y = bias[c + 1]; acc.z = bias[c + 2]; acc.w = bias[c + 3];
#pragma unroll
    for (int j = 0; j < 3; j++) {
        const int ss = s - 1 + j;
        if (ss < 0 || ss >= SSZ) continue;
        const float4 xv = *(const float4*)(x + (size_t)(bs + (j - 1)) * DIM + c);
        acc.x += xv.x * w[(c + 0) * 3 + j];
        acc.y += xv.y * w[(c + 1) * 3 + j];
        acc.z += xv.z * w[(c + 2) * 3 + j];
        acc.w += xv.w * w[(c + 3) * 3 + j];
    }
    *(float4*)(y + (size_t)bs * DIM + c) = acc;
}

// ===================== flash attention, fp32 FFMA2, BM=BN=64, hd=64 ========
__device__ __forceinline__ float redmax16(float v) {
#pragma unroll
    for (int o = 8; o > 0; o >>= 1)
        v = fmaxf(v, __shfl_xor_sync(0xffffffffu, v, o, 16));
    return v;
}
__device__ __forceinline__ float redsum16(float v) {
#pragma unroll
    for (int o = 8; o > 0; o >>= 1)
        v += __shfl_xor_sync(0xffffffffu, v, o, 16);
    return v;
}

#define QKS 68   // stride for transposed Q/K tiles: 16B-aligned rows

__global__ __launch_bounds__(256) void flash_attn(
    const float* __restrict__ Qg, const float* __restrict__ Kg,
    const float* __restrict__ Vg, float* __restrict__ Og)
{
    extern __shared__ float sm[];
    float* Qs = sm;                  // [k][r]   stride QKS
    float* Ks = sm + 64 * QKS;       // [k][c]   stride QKS
    float* Vs = sm + 2 * 64 * QKS;   // [key][c] stride 64
    float* Ps = Vs + 64 * 64;        // [r][key] stride 64

    const int tid = threadIdx.x;
    const int ty = tid >> 4, tx = tid & 15;
    const int bh = blockIdx.y;
    const int b = bh >> 4, h = bh & 15;
    const int q0 = blockIdx.x * 64;

    const float* qb = Qg + ((size_t)(b * SSZ + q0)) * DIM + h * HDIM;

#pragma unroll
    for (int it = 0; it < 4; it++) {
        const int r = (tid >> 4) + it * 16;
        const int c = (tid & 15) * 4;
        const float4 v = *(const float4*)(qb + (size_t)r * DIM + c);
        Qs[(c + 0) * QKS + r] = v.x;
        Qs[(c + 1) * QKS + r] = v.y;
        Qs[(c + 2) * QKS + r] = v.z;
        Qs[(c + 3) * QKS + r] = v.w;
    }

    float m_i[4], l_i[4];
    u64t  o2[4][2];
#pragma unroll
    for (int i = 0; i < 4; i++) {
        m_i[i] = -1e30f; l_i[i] = 0.0f;
        o2[i][0] = 0ull; o2[i][1] = 0ull;
    }

    for (int tkv = 0; tkv < SSZ / 64; tkv++) {
        __syncthreads();
        const float* kb = Kg + ((size_t)(b * SSZ + tkv * 64)) * DIM + h * HDIM;
        const float* vb = Vg + ((size_t)(b * SSZ + tkv * 64)) * DIM + h * HDIM;
#pragma unroll
        for (int it = 0; it < 4; it++) {
            const int r = (tid >> 4) + it * 16;
            const int c = (tid & 15) * 4;
            const float4 kv = *(const float4*)(kb + (size_t)r * DIM + c);
            Ks[(c + 0) * QKS + r] = kv.x;
            Ks[(c + 1) * QKS + r] = kv.y;
            Ks[(c + 2) * QKS + r] = kv.z;
            Ks[(c + 3) * QKS + r] = kv.w;
            const float4 vv = *(const float4*)(vb + (size_t)r * DIM + c);
            *(float4*)&Vs[r * 64 + c] = vv;
        }
        __syncthreads();

        u64t s2[4][2];
#pragma unroll
        for (int i = 0; i < 4; i++) { s2[i][0] = 0ull; s2[i][1] = 0ull; }

#pragma unroll 4
        for (int k = 0; k < HDIM; k++) {
            const float4 av = *(const float4*)&Qs[k * QKS + ty * 4];
            const ulonglong2 bv = *(const ulonglong2*)&Ks[k * QKS + tx * 4];
            u64t ad[4];
            DUP2(ad[0], av.x); DUP2(ad[1], av.y);
            DUP2(ad[2], av.z); DUP2(ad[3], av.w);
#pragma unroll
            for (int i = 0; i < 4; i++) {
                FMA2(s2[i][0], ad[i], bv.x);
                FMA2(s2[i][1], ad[i], bv.y);
            }
        }

        float s[4][4], rs[4];
#pragma unroll
        for (int i = 0; i < 4; i++) {
            UNPK2(s[i][0], s[i][1], s2[i][0]);
            UNPK2(s[i][2], s[i][3], s2[i][1]);
        }
#pragma unroll
        for (int i = 0; i < 4; i++) {
            float mt = -1e30f;
#pragma unroll
            for (int j = 0; j < 4; j++) {
                s[i][j] *= 0.125f;
                mt = fmaxf(mt, s[i][j]);
            }
            mt = redmax16(mt);
            const float mn = fmaxf(m_i[i], mt);
            const float al = __expf(m_i[i] - mn);
            float r = 0.0f;
#pragma unroll
            for (int j = 0; j < 4; j++) {
                const float p = __expf(s[i][j] - mn);
                s[i][j] = p; r += p;
            }
            r = redsum16(r);
            l_i[i] = l_i[i] * al + r;
            m_i[i] = mn;
            rs[i] = al;
        }
#pragma unroll
        for (int i = 0; i < 4; i++) {
            u64t rsd; DUP2(rsd, rs[i]);
            MUL2(o2[i][0], rsd);
            MUL2(o2[i][1], rsd);
        }

#pragma unroll
        for (int i = 0; i < 4; i++)
#pragma unroll
            for (int j = 0; j < 4; j++)
                Ps[(ty * 4 + i) * 64 + tx * 4 + j] = s[i][j];
        __syncthreads();

#pragma unroll 4
        for (int kk = 0; kk < 64; kk++) {
            const ulonglong2 vv = *(const ulonglong2*)&Vs[kk * 64 + tx * 4];
            u64t pd[4];
            DUP2(pd[0], Ps[(ty * 4 + 0) * 64 + kk]);
            DUP2(pd[1], Ps[(ty * 4 + 1) * 64 + kk]);
            DUP2(pd[2], Ps[(ty * 4 + 2) * 64 + kk]);
            DUP2(pd[3], Ps[(ty * 4 + 3) * 64 + kk]);
#pragma unroll
            for (int i = 0; i < 4; i++) {
                FMA2(o2[i][0], pd[i], vv.x);
                FMA2(o2[i][1], pd[i], vv.y);
            }
        }
    }

    float* ob = Og + ((size_t)(b * SSZ + q0)) * DIM + h * HDIM;
#pragma unroll
    for (int i = 0; i < 4; i++) {
        const float inv = 1.0f / l_i[i];
        float o[4];
        UNPK2(o[0], o[1], o2[i][0]);
        UNPK2(o[2], o[3], o2[i][1]);
#pragma unroll
        for (int j = 0; j < 4; j++)
            ob[(size_t)(ty * 4 + i) * DIM + tx * 4 + j] = o[j] * inv;
    }
}

// ===================== launcher ============================================
extern "C" void kernel_launch(void* const* d_in, const int* in_sizes, int n_in,
                              void* d_out, int out_size)
{
    const float* x    = (const float*)d_in[0];
    const float* wq   = (const float*)d_in[1];
    const float* bq   = (const float*)d_in[2];
    const float* wk   = (const float*)d_in[3];
    const float* bk   = (const float*)d_in[4];
    const float* wv   = (const float*)d_in[5];
    const float* bv   = (const float*)d_in[6];
    const float* wo   = (const float*)d_in[7];
    const float* bo   = (const float*)d_in[8];
    const float* dw_w = (const float*)d_in[9];
    const float* dw_b = (const float*)d_in[10];
    const float* pw_w = (const float*)d_in[11];
    const float* pw_b = (const float*)d_in[12];
    const float* fu_w = (const float*)d_in[13];
    const float* fu_b = (const float*)d_in[14];
    float* out = (float*)d_out;

    float *q, *k, *v, *c1, *c2, *at, *ao;
    cudaGetSymbolAddress((void**)&q,  g_q);
    cudaGetSymbolAddress((void**)&k,  g_k);
    cudaGetSymbolAddress((void**)&v,  g_v);
    cudaGetSymbolAddress((void**)&c1, g_c1);
    cudaGetSymbolAddress((void**)&c2, g_c2);
    cudaGetSymbolAddress((void**)&at, g_at);
    cudaGetSymbolAddress((void**)&ao, g_ao);

    const dim3 gg(DIM / 128, MROWS / 128);   // (8, 32)
    const int BIG = 1 << 30;

    // Q/K/V projections
    gemm_nt<0><<<gg, 256>>>(x, x, BIG, wq, DIM, bq, q, MROWS, DIM, DIM, DIM);
    gemm_nt<0><<<gg, 256>>>(x, x, BIG, wk, DIM, bk, k, MROWS, DIM, DIM, DIM);
    gemm_nt<0><<<gg, 256>>>(x, x, BIG, wv, DIM, bv, v, MROWS, DIM, DIM, DIM);

    // conv branch
    const int dwthreads = BSZ * SSZ * (DIM / 4);
    dwconv_kernel<<<(dwthreads + 255) / 256, 256>>>(x, dw_w, dw_b, c1);
    gemm_nt<1><<<gg, 256>>>(c1, c1, BIG, pw_w, DIM, pw_b, c2, MROWS, DIM, DIM, DIM);

    // attention
    const size_t fsm = (size_t)(2 * 64 * QKS + 2 * 64 * 64) * sizeof(float);
    cudaFuncSetAttribute(flash_attn, cudaFuncAttributeMaxDynamicSharedMemorySize,
                         (int)fsm);
    flash_attn<<<dim3(SSZ / 64, BSZ * NHEAD), 256, fsm>>>(q, k, v, at);
    gemm_nt<0><<<gg, 256>>>(at, at, BIG, wo, DIM, bo, ao, MROWS, DIM, DIM, DIM);

    // fusion: concat([attn_o, conv], K) @ fu_w^T + fu_b
    // ksplit = DIM: k < 1024 reads ao, k >= 1024 reads c2.
    gemm_nt<0><<<gg, 256>>>(ao, c2, DIM, fu_w, 2 * DIM, fu_b, out,
                            MROWS, DIM, 2 * DIM, DIM);
}

// round 16
// speedup vs baseline: 2.2067x; 1.4342x over previous
#include <cuda_runtime.h>
#include <cuda_bf16.h>
#include <math.h>

// Problem constants
#define BSZ 2
#define SSZ 2048
#define DIM 1024
#define NHEAD 16
#define HDIM 64
#define MROWS (BSZ * SSZ)   // 4096

typedef unsigned int       u32;
typedef unsigned long long u64t;

// ---- bf16 mma m16n8k16, fp32 accumulate ------------------------------------
// a0=(row g, k lo), a1=(row g+8, k lo), a2=(row g, k hi), a3=(row g+8, k hi)
#define MMA_BF16(c, a, b0v, b1v) \
    asm("mma.sync.aligned.m16n8k16.row.col.f32.bf16.bf16.f32 " \
        "{%0,%1,%2,%3}, {%4,%5,%6,%7}, {%8,%9}, {%0,%1,%2,%3};" \
        : "+f"((c)[0]), "+f"((c)[1]), "+f"((c)[2]), "+f"((c)[3]) \
        : "r"((a)[0]), "r"((a)[1]), "r"((a)[2]), "r"((a)[3]), \
          "r"(b0v), "r"(b1v))

#define LDSM4T(d0, d1, d2, d3, a) \
    asm volatile("ldmatrix.sync.aligned.m8n8.x4.trans.shared.b16 " \
                 "{%0,%1,%2,%3}, [%4];" \
                 : "=r"(d0), "=r"(d1), "=r"(d2), "=r"(d3) : "r"(a))

__device__ __forceinline__ u32 pack_bf2(__nv_bfloat16 a, __nv_bfloat16 b) {
    __nv_bfloat162 p = __halves2bfloat162(a, b);
    return *reinterpret_cast<u32*>(&p);
}

// split one float into bf16 hi + bf16 lo (lo = residual)
__device__ __forceinline__ void split_bf(float v, __nv_bfloat16& hi, __nv_bfloat16& lo) {
    hi = __float2bfloat16_rn(v);
    lo = __float2bfloat16_rn(v - __bfloat162float(hi));
}

// -------------------- scratch (__device__ globals; no allocation) -----------
__device__ float g_q [MROWS * DIM];
__device__ float g_k [MROWS * DIM];
__device__ float g_v [MROWS * DIM];
__device__ float g_c1[MROWS * DIM];   // depthwise conv out
__device__ float g_c2[MROWS * DIM];   // pointwise conv + GELU out
__device__ float g_at[MROWS * DIM];   // attention out (pre o-proj)
__device__ float g_ao[MROWS * DIM];   // after wo

// ===================== GEMM (NT) via bf16-split tensor cores ================
// (unchanged from round 7 — validated)
template<int ACT>
__global__ __launch_bounds__(256) void gemm_nt(
    const float* __restrict__ A0, const float* __restrict__ A1, int ksplit,
    const float* __restrict__ W, int ldw,
    const float* __restrict__ bias, float* __restrict__ Cc,
    int M, int N, int K, int lda)
{
    __shared__ u32 Ah[128][20];
    __shared__ u32 Al[128][20];
    __shared__ u32 Bh[128][20];
    __shared__ u32 Bl[128][20];

    const int tid  = threadIdx.x;
    const int m0   = blockIdx.y * 128;
    const int n0   = blockIdx.x * 128;
    const int wid  = tid >> 5;
    const int lane = tid & 31;
    const int wm   = (wid & 3) * 32;
    const int wn   = (wid >> 2) * 64;
    const int g    = lane >> 2;
    const int t    = lane & 3;

    const int lrow = tid >> 3;
    const int lkq  = tid & 7;

    float acc[2][8][4];
#pragma unroll
    for (int mt = 0; mt < 2; mt++)
#pragma unroll
        for (int nt = 0; nt < 8; nt++)
#pragma unroll
            for (int e = 0; e < 4; e++) acc[mt][nt][e] = 0.0f;

    for (int k0 = 0; k0 < K; k0 += 32) {
        __syncthreads();
#pragma unroll
        for (int it = 0; it < 4; it++) {
            const int row = lrow + 32 * it;
            const int kk  = k0 + lkq * 4;
            const float* ap = (kk < ksplit)
                ? (A0 + (size_t)(m0 + row) * lda + kk)
                : (A1 + (size_t)(m0 + row) * lda + (kk - ksplit));
            const float4 av = *(const float4*)ap;
            {
                __nv_bfloat16 hx, lx, hy, ly, hz, lz, hw, lw;
                split_bf(av.x, hx, lx); split_bf(av.y, hy, ly);
                split_bf(av.z, hz, lz); split_bf(av.w, hw, lw);
                Ah[row][lkq * 2 + 0] = pack_bf2(hx, hy);
                Ah[row][lkq * 2 + 1] = pack_bf2(hz, hw);
                Al[row][lkq * 2 + 0] = pack_bf2(lx, ly);
                Al[row][lkq * 2 + 1] = pack_bf2(lz, lw);
            }
            const float4 bv = *(const float4*)(W + (size_t)(n0 + row) * ldw + kk);
            {
                __nv_bfloat16 hx, lx, hy, ly, hz, lz, hw, lw;
                split_bf(bv.x, hx, lx); split_bf(bv.y, hy, ly);
                split_bf(bv.z, hz, lz); split_bf(bv.w, hw, lw);
                Bh[row][lkq * 2 + 0] = pack_bf2(hx, hy);
                Bh[row][lkq * 2 + 1] = pack_bf2(hz, hw);
                Bl[row][lkq * 2 + 0] = pack_bf2(lx, ly);
                Bl[row][lkq * 2 + 1] = pack_bf2(lz, lw);
            }
        }
        __syncthreads();

#pragma unroll
        for (int ks = 0; ks < 2; ks++) {
            const int kb = ks * 8;
            u32 ah[2][4], al[2][4];
#pragma unroll
            for (int mt = 0; mt < 2; mt++) {
                const int r = wm + mt * 16;
                ah[mt][0] = Ah[r + g    ][kb + t];
                ah[mt][1] = Ah[r + 8 + g][kb + t];
                ah[mt][2] = Ah[r + g    ][kb + t + 4];
                ah[mt][3] = Ah[r + 8 + g][kb + t + 4];
                al[mt][0] = Al[r + g    ][kb + t];
                al[mt][1] = Al[r + 8 + g][kb + t];
                al[mt][2] = Al[r + g    ][kb + t + 4];
                al[mt][3] = Al[r + 8 + g][kb + t + 4];
            }
#pragma unroll
            for (int nt = 0; nt < 8; nt++) {
                const int c = wn + nt * 8;
                const u32 bh0 = Bh[c + g][kb + t];
                const u32 bh1 = Bh[c + g][kb + t + 4];
                const u32 bl0 = Bl[c + g][kb + t];
                const u32 bl1 = Bl[c + g][kb + t + 4];
#pragma unroll
                for (int mt = 0; mt < 2; mt++) {
                    MMA_BF16(acc[mt][nt], ah[mt], bh0, bh1);
                    MMA_BF16(acc[mt][nt], ah[mt], bl0, bl1);
                    MMA_BF16(acc[mt][nt], al[mt], bh0, bh1);
                }
            }
        }
    }

#pragma unroll
    for (int mt = 0; mt < 2; mt++) {
#pragma unroll
        for (int nt = 0; nt < 8; nt++) {
            const int row = m0 + wm + mt * 16 + g;
            const int col = n0 + wn + nt * 8 + 2 * t;
            float v0 = acc[mt][nt][0] + bias[col];
            float v1 = acc[mt][nt][1] + bias[col + 1];
            float v2 = acc[mt][nt][2] + bias[col];
            float v3 = acc[mt][nt][3] + bias[col + 1];
            if (ACT == 1) {
                v0 = 0.5f * v0 * (1.0f + erff(v0 * 0.70710678118654752f));
                v1 = 0.5f * v1 * (1.0f + erff(v1 * 0.70710678118654752f));
                v2 = 0.5f * v2 * (1.0f + erff(v2 * 0.70710678118654752f));
                v3 = 0.5f * v3 * (1.0f + erff(v3 * 0.70710678118654752f));
            }
            *(float2*)(Cc + (size_t)row * N + col)       = make_float2(v0, v1);
            *(float2*)(Cc + (size_t)(row + 8) * N + col) = make_float2(v2, v3);
        }
    }
}

// ===================== depthwise conv (K=3, pad=1) along S =================
__global__ void dwconv_kernel(
    const float* __restrict__ x, const float* __restrict__ w,
    const float* __restrict__ bias, float* __restrict__ y)
{
    const int C4 = DIM / 4;
    int idx = blockIdx.x * blockDim.x + threadIdx.x;
    if (idx >= BSZ * SSZ * C4) return;
    const int c  = (idx % C4) * 4;
    const int bs = idx / C4;
    const int s  = bs & (SSZ - 1);

    float4 acc;
    acc.x = bias[c]; acc.y = bias[c + 1]; acc.z = bias[c + 2]; acc.w = bias[c + 3];
#pragma unroll
    for (int j = 0; j < 3; j++) {
        const int ss = s - 1 + j;
        if (ss < 0 || ss >= SSZ) continue;
        const float4 xv = *(const float4*)(x + (size_t)(bs + (j - 1)) * DIM + c);
        acc.x += xv.x * w[(c + 0) * 3 + j];
        acc.y += xv.y * w[(c + 1) * 3 + j];
        acc.z += xv.z * w[(c + 2) * 3 + j];
        acc.w += xv.w * w[(c + 3) * 3 + j];
    }
    *(float4*)(y + (size_t)bs * DIM + c) = acc;
}

// ===================== flash attention, bf16-split tensor cores ============
// BM=128 (8 warps x m16), BN=64 keys/tile, hd=64.
// smem planes stored [row][hd-kpair] stride 36 u32 (conflict-free frags).
// S = QK^T and O += PV both 3-term split mma; P repacked in registers;
// V B-fragments via ldmatrix.x4.trans from natural [key][hd] layout.
#define FQP 36   // u32 row stride for all planes

__global__ __launch_bounds__(256) void flash_attn(
    const float* __restrict__ Qg, const float* __restrict__ Kg,
    const float* __restrict__ Vg, float* __restrict__ Og)
{
    extern __shared__ u32 dsm[];
    u32* Qh = dsm;                  // [128][FQP]
    u32* Ql = Qh + 128 * FQP;
    u32* Kh = Ql + 128 * FQP;       // [64][FQP]
    u32* Kl = Kh + 64 * FQP;
    u32* Vh = Kl + 64 * FQP;        // [64][FQP]
    u32* Vl = Vh + 64 * FQP;

    const int tid  = threadIdx.x;
    const int wid  = tid >> 5;
    const int lane = tid & 31;
    const int g    = lane >> 2;
    const int t    = lane & 3;
    const int wm   = wid * 16;          // warp row base within 128

    const int bh = blockIdx.y;
    const int b = bh >> 4, h = bh & 15;
    const int q0 = blockIdx.x * 128;

    // ---- load Q (128 x 64) into hi/lo planes ----
    const float* qb = Qg + ((size_t)(b * SSZ + q0)) * DIM + h * HDIM;
#pragma unroll
    for (int i = 0; i < 8; i++) {
        const int idx = tid + 256 * i;      // 0..2047
        const int r   = idx >> 4;           // 0..127
        const int c4  = idx & 15;           // float4 idx
        const float4 v = *(const float4*)(qb + (size_t)r * DIM + c4 * 4);
        __nv_bfloat16 hx, lx, hy, ly, hz, lz, hw, lw;
        split_bf(v.x, hx, lx); split_bf(v.y, hy, ly);
        split_bf(v.z, hz, lz); split_bf(v.w, hw, lw);
        Qh[r * FQP + c4 * 2 + 0] = pack_bf2(hx, hy);
        Qh[r * FQP + c4 * 2 + 1] = pack_bf2(hz, hw);
        Ql[r * FQP + c4 * 2 + 0] = pack_bf2(lx, ly);
        Ql[r * FQP + c4 * 2 + 1] = pack_bf2(lz, lw);
    }

    // ldmatrix per-lane address components for V (byte offsets into Vh/Vl)
    const int mi     = lane >> 3;           // matrix index 0..3
    const int mr     = lane & 7;
    const int keyoff = ((mi & 1) << 3) + mr;   // 0..15
    const int ntsel  = mi >> 1;                // 0 or 1
    const u32 vh_base = (u32)__cvta_generic_to_shared(Vh);
    const u32 vl_base = (u32)__cvta_generic_to_shared(Vl);

    float m_[2] = { -1e30f, -1e30f };
    float l_[2] = { 0.0f, 0.0f };
    float oacc[8][4];
#pragma unroll
    for (int nt = 0; nt < 8; nt++)
#pragma unroll
        for (int e = 0; e < 4; e++) oacc[nt][e] = 0.0f;

    for (int tkv = 0; tkv < SSZ / 64; tkv++) {
        __syncthreads();   // previous PV done before overwriting K/V
        const float* kb = Kg + ((size_t)(b * SSZ + tkv * 64)) * DIM + h * HDIM;
        const float* vb = Vg + ((size_t)(b * SSZ + tkv * 64)) * DIM + h * HDIM;
#pragma unroll
        for (int i = 0; i < 4; i++) {
            const int idx = tid + 256 * i;   // 0..1023
            const int r   = idx >> 4;        // key 0..63
            const int c4  = idx & 15;
            {
                const float4 v = *(const float4*)(kb + (size_t)r * DIM + c4 * 4);
                __nv_bfloat16 hx, lx, hy, ly, hz, lz, hw, lw;
                split_bf(v.x, hx, lx); split_bf(v.y, hy, ly);
                split_bf(v.z, hz, lz); split_bf(v.w, hw, lw);
                Kh[r * FQP + c4 * 2 + 0] = pack_bf2(hx, hy);
                Kh[r * FQP + c4 * 2 + 1] = pack_bf2(hz, hw);
                Kl[r * FQP + c4 * 2 + 0] = pack_bf2(lx, ly);
                Kl[r * FQP + c4 * 2 + 1] = pack_bf2(lz, lw);
            }
            {
                const float4 v = *(const float4*)(vb + (size_t)r * DIM + c4 * 4);
                __nv_bfloat16 hx, lx, hy, ly, hz, lz, hw, lw;
                split_bf(v.x, hx, lx); split_bf(v.y, hy, ly);
                split_bf(v.z, hz, lz); split_bf(v.w, hw, lw);
                Vh[r * FQP + c4 * 2 + 0] = pack_bf2(hx, hy);
                Vh[r * FQP + c4 * 2 + 1] = pack_bf2(hz, hw);
                Vl[r * FQP + c4 * 2 + 0] = pack_bf2(lx, ly);
                Vl[r * FQP + c4 * 2 + 1] = pack_bf2(lz, lw);
            }
        }
        __syncthreads();

        // ---- S = Q K^T (3-term split), warp computes 16 x 64 ----
        float sacc[8][4];
#pragma unroll
        for (int nt = 0; nt < 8; nt++)
#pragma unroll
            for (int e = 0; e < 4; e++) sacc[nt][e] = 0.0f;

#pragma unroll
        for (int kc = 0; kc < 4; kc++) {
            const int kb8 = kc * 8;
            u32 ah[4], al[4];
            ah[0] = Qh[(wm + g    ) * FQP + kb8 + t];
            ah[1] = Qh[(wm + 8 + g) * FQP + kb8 + t];
            ah[2] = Qh[(wm + g    ) * FQP + kb8 + t + 4];
            ah[3] = Qh[(wm + 8 + g) * FQP + kb8 + t + 4];
            al[0] = Ql[(wm + g    ) * FQP + kb8 + t];
            al[1] = Ql[(wm + 8 + g) * FQP + kb8 + t];
            al[2] = Ql[(wm + g    ) * FQP + kb8 + t + 4];
            al[3] = Ql[(wm + 8 + g) * FQP + kb8 + t + 4];
#pragma unroll
            for (int nt = 0; nt < 8; nt++) {
                const int kr = nt * 8 + g;   // key row
                const u32 bh0 = Kh[kr * FQP + kb8 + t];
                const u32 bh1 = Kh[kr * FQP + kb8 + t + 4];
                const u32 bl0 = Kl[kr * FQP + kb8 + t];
                const u32 bl1 = Kl[kr * FQP + kb8 + t + 4];
                MMA_BF16(sacc[nt], ah, bh0, bh1);
                MMA_BF16(sacc[nt], ah, bl0, bl1);
                MMA_BF16(sacc[nt], al, bh0, bh1);
            }
        }

        // ---- online softmax (rows wm+g and wm+8+g) ----
        float mt0 = -1e30f, mt1 = -1e30f;
#pragma unroll
        for (int nt = 0; nt < 8; nt++) {
#pragma unroll
            for (int e = 0; e < 4; e++) sacc[nt][e] *= 0.125f;
            mt0 = fmaxf(mt0, fmaxf(sacc[nt][0], sacc[nt][1]));
            mt1 = fmaxf(mt1, fmaxf(sacc[nt][2], sacc[nt][3]));
        }
#pragma unroll
        for (int o = 1; o <= 2; o <<= 1) {
            mt0 = fmaxf(mt0, __shfl_xor_sync(0xffffffffu, mt0, o));
            mt1 = fmaxf(mt1, __shfl_xor_sync(0xffffffffu, mt1, o));
        }
        const float mn0 = fmaxf(m_[0], mt0);
        const float mn1 = fmaxf(m_[1], mt1);
        const float al0 = __expf(m_[0] - mn0);
        const float al1 = __expf(m_[1] - mn1);
        float r0 = 0.0f, r1 = 0.0f;
#pragma unroll
        for (int nt = 0; nt < 8; nt++) {
            sacc[nt][0] = __expf(sacc[nt][0] - mn0);
            sacc[nt][1] = __expf(sacc[nt][1] - mn0);
            sacc[nt][2] = __expf(sacc[nt][2] - mn1);
            sacc[nt][3] = __expf(sacc[nt][3] - mn1);
            r0 += sacc[nt][0] + sacc[nt][1];
            r1 += sacc[nt][2] + sacc[nt][3];
        }
#pragma unroll
        for (int o = 1; o <= 2; o <<= 1) {
            r0 += __shfl_xor_sync(0xffffffffu, r0, o);
            r1 += __shfl_xor_sync(0xffffffffu, r1, o);
        }
        l_[0] = l_[0] * al0 + r0;
        l_[1] = l_[1] * al1 + r1;
        m_[0] = mn0;
        m_[1] = mn1;
#pragma unroll
        for (int nt = 0; nt < 8; nt++) {
            oacc[nt][0] *= al0; oacc[nt][1] *= al0;
            oacc[nt][2] *= al1; oacc[nt][3] *= al1;
        }

        // ---- O += P V (3-term split), P repacked from sacc in registers ----
#pragma unroll
        for (int kc = 0; kc < 4; kc++) {
            u32 pah[4], pal[4];
            {
                __nv_bfloat16 h0, l0, h1, l1;
                split_bf(sacc[2 * kc][0], h0, l0);
                split_bf(sacc[2 * kc][1], h1, l1);
                pah[0] = pack_bf2(h0, h1); pal[0] = pack_bf2(l0, l1);
                split_bf(sacc[2 * kc][2], h0, l0);
                split_bf(sacc[2 * kc][3], h1, l1);
                pah[1] = pack_bf2(h0, h1); pal[1] = pack_bf2(l0, l1);
                split_bf(sacc[2 * kc + 1][0], h0, l0);
                split_bf(sacc[2 * kc + 1][1], h1, l1);
                pah[2] = pack_bf2(h0, h1); pal[2] = pack_bf2(l0, l1);
                split_bf(sacc[2 * kc + 1][2], h0, l0);
                split_bf(sacc[2 * kc + 1][3], h1, l1);
                pah[3] = pack_bf2(h0, h1); pal[3] = pack_bf2(l0, l1);
            }
            const u32 rowbyte = (u32)(((16 * kc + keyoff) * FQP) * 4);
#pragma unroll
            for (int np = 0; np < 4; np++) {
                const u32 off = rowbyte + (u32)(((2 * np + ntsel) * 4) * 4);
                u32 vh0a, vh1a, vh0b, vh1b;
                u32 vl0a, vl1a, vl0b, vl1b;
                LDSM4T(vh0a, vh1a, vh0b, vh1b, vh_base + off);
                LDSM4T(vl0a, vl1a, vl0b, vl1b, vl_base + off);
                MMA_BF16(oacc[2 * np],     pah, vh0a, vh1a);
                MMA_BF16(oacc[2 * np],     pah, vl0a, vl1a);
                MMA_BF16(oacc[2 * np],     pal, vh0a, vh1a);
                MMA_BF16(oacc[2 * np + 1], pah, vh0b, vh1b);
                MMA_BF16(oacc[2 * np + 1], pah, vl0b, vl1b);
                MMA_BF16(oacc[2 * np + 1], pal, vh0b, vh1b);
            }
        }
    }

    // ---- epilogue: divide by l, store ----
    const float inv0 = 1.0f / l_[0];
    const float inv1 = 1.0f / l_[1];
    float* ob = Og + ((size_t)(b * SSZ + q0)) * DIM + h * HDIM;
#pragma unroll
    for (int nt = 0; nt < 8; nt++) {
        const int col = nt * 8 + 2 * t;
        const int ra = wm + g, rb = wm + 8 + g;
        *(float2*)(ob + (size_t)ra * DIM + col) =
            make_float2(oacc[nt][0] * inv0, oacc[nt][1] * inv0);
        *(float2*)(ob + (size_t)rb * DIM + col) =
            make_float2(oacc[nt][2] * inv1, oacc[nt][3] * inv1);
    }
}

// ===================== launcher ============================================
extern "C" void kernel_launch(void* const* d_in, const int* in_sizes, int n_in,
                              void* d_out, int out_size)
{
    const float* x    = (const float*)d_in[0];
    const float* wq   = (const float*)d_in[1];
    const float* bq   = (const float*)d_in[2];
    const float* wk   = (const float*)d_in[3];
    const float* bk   = (const float*)d_in[4];
    const float* wv   = (const float*)d_in[5];
    const float* bv   = (const float*)d_in[6];
    const float* wo   = (const float*)d_in[7];
    const float* bo   = (const float*)d_in[8];
    const float* dw_w = (const float*)d_in[9];
    const float* dw_b = (const float*)d_in[10];
    const float* pw_w = (const float*)d_in[11];
    const float* pw_b = (const float*)d_in[12];
    const float* fu_w = (const float*)d_in[13];
    const float* fu_b = (const float*)d_in[14];
    float* out = (float*)d_out;

    float *q, *k, *v, *c1, *c2, *at, *ao;
    cudaGetSymbolAddress((void**)&q,  g_q);
    cudaGetSymbolAddress((void**)&k,  g_k);
    cudaGetSymbolAddress((void**)&v,  g_v);
    cudaGetSymbolAddress((void**)&c1, g_c1);
    cudaGetSymbolAddress((void**)&c2, g_c2);
    cudaGetSymbolAddress((void**)&at, g_at);
    cudaGetSymbolAddress((void**)&ao, g_ao);

    const dim3 gg(DIM / 128, MROWS / 128);   // (8, 32)
    const int BIG = 1 << 30;

    // Q/K/V projections
    gemm_nt<0><<<gg, 256>>>(x, x, BIG, wq, DIM, bq, q, MROWS, DIM, DIM, DIM);
    gemm_nt<0><<<gg, 256>>>(x, x, BIG, wk, DIM, bk, k, MROWS, DIM, DIM, DIM);
    gemm_nt<0><<<gg, 256>>>(x, x, BIG, wv, DIM, bv, v, MROWS, DIM, DIM, DIM);

    // conv branch
    const int dwthreads = BSZ * SSZ * (DIM / 4);
    dwconv_kernel<<<(dwthreads + 255) / 256, 256>>>(x, dw_w, dw_b, c1);
    gemm_nt<1><<<gg, 256>>>(c1, c1, BIG, pw_w, DIM, pw_b, c2, MROWS, DIM, DIM, DIM);

    // attention (BM=128): smem = 6 planes = 73728 B dynamic
    const int fsm = (2 * 128 * FQP + 4 * 64 * FQP) * (int)sizeof(u32);
    cudaFuncSetAttribute(flash_attn, cudaFuncAttributeMaxDynamicSharedMemorySize,
                         fsm);
    flash_attn<<<dim3(SSZ / 128, BSZ * NHEAD), 256, fsm>>>(q, k, v, at);
    gemm_nt<0><<<gg, 256>>>(at, at, BIG, wo, DIM, bo, ao, MROWS, DIM, DIM, DIM);

    // fusion: concat([attn_o, conv], K) @ fu_w^T + fu_b
    gemm_nt<0><<<gg, 256>>>(ao, c2, DIM, fu_w, 2 * DIM, fu_b, out,
                            MROWS, DIM, 2 * DIM, DIM);
}